// round 11
// baseline (speedup 1.0000x reference)
#include <cuda_runtime.h>
#include <cuda_fp16.h>
#include <cstdint>

#define TOKENS 16384
#define HIDDEN 4096
#define NB 8
#define BLK 512

#define BM 128
#define NT 4                 // n-tiles per CTA (BN=128 each)
#define BK 64                // k halfs per stage -> 128B smem rows
#define NSTAGE (BLK / BK)    // 8
#define TOTAL_S (NT * NSTAGE)// 32
#define RING 3
#define THREADS 512

#define SLOT_BYTES (128 * 128)                     // 16384
#define SMEM_A 0                                   // 8 permanent A slots
#define SMEM_B (NSTAGE * SLOT_BYTES)               // 131072
#define SMEM_TOTAL (SMEM_B + RING * SLOT_BYTES)    // 180224

__device__ __half g_Wt[NB * BLK * BLK];            // W transposed to [n][k], fp16

__device__ __forceinline__ uint32_t smem_u32(const void* p) {
    uint32_t a;
    asm("{ .reg .u64 t; cvta.to.shared.u64 t, %1; cvt.u32.u64 %0, t; }" : "=r"(a) : "l"(p));
    return a;
}
__device__ __forceinline__ void ldm4(uint32_t& r0, uint32_t& r1, uint32_t& r2,
                                     uint32_t& r3, uint32_t addr) {
    asm volatile("ldmatrix.sync.aligned.m8n8.x4.shared.b16 {%0,%1,%2,%3}, [%4];"
                 : "=r"(r0), "=r"(r1), "=r"(r2), "=r"(r3) : "r"(addr));
}
__device__ __forceinline__ void mma_f16(float c[4], uint32_t a0, uint32_t a1,
                                        uint32_t a2, uint32_t a3,
                                        uint32_t b0, uint32_t b1) {
    asm volatile(
        "mma.sync.aligned.m16n8k16.row.col.f32.f16.f16.f32 "
        "{%0,%1,%2,%3}, {%4,%5,%6,%7}, {%8,%9}, {%0,%1,%2,%3};\n"
        : "+f"(c[0]), "+f"(c[1]), "+f"(c[2]), "+f"(c[3])
        : "r"(a0), "r"(a1), "r"(a2), "r"(a3), "r"(b0), "r"(b1));
}
__device__ __forceinline__ void cp16(uint32_t dst, const void* src) {
    asm volatile("cp.async.cg.shared.global [%0], [%1], 16;" :: "r"(dst), "l"(src) : "memory");
}
#define CP_COMMIT() asm volatile("cp.async.commit_group;" ::: "memory")
#define CP_WAIT1()  asm volatile("cp.async.wait_group 1;" ::: "memory")

// ---------------- prepass: W transpose + fp16 (4 MB traffic, ~4us) ----------------
__global__ void transpose_half_kernel(const float* __restrict__ W) {
    __shared__ float t[32][33];
    const int z = blockIdx.z;
    const int k0 = blockIdx.x * 32, n0 = blockIdx.y * 32;
    const float* Wz = W + (size_t)z * BLK * BLK;
    __half* Wtz = g_Wt + (size_t)z * BLK * BLK;
    const int tx = threadIdx.x, ty = threadIdx.y;
#pragma unroll
    for (int i = 0; i < 32; i += 8)
        t[ty + i][tx] = Wz[(size_t)(k0 + ty + i) * BLK + n0 + tx];
    __syncthreads();
#pragma unroll
    for (int i = 0; i < 32; i += 8)
        Wtz[(size_t)(n0 + ty + i) * BLK + k0 + tx] = __float2half_rn(t[tx][ty + i]);
}

// ---------------- main kernel: A-resident, fused cvt, 16 warps ----------------
__global__ void __launch_bounds__(THREADS, 1)
tp_fp16_kernel(const float* __restrict__ X, float* __restrict__ O)
{
    extern __shared__ char smem[];
    const uint32_t sb = smem_u32(smem);
    const int tid  = threadIdx.x;
    const int lane = tid & 31;
    const int wid  = tid >> 5;          // 0..15
    const int m0w  = (wid & 3) * 32;    // 4 m-warps
    const int n0w  = (wid >> 2) * 32;   // 4 n-warps

    const int m_base = blockIdx.x * BM;
    const int bz     = blockIdx.y;

    // ---- staging plan: 512 threads -> rows (s_r + 64i), one 16B chunk each ----
    const int s_r = tid >> 3;           // 0..63
    const int s_c = tid & 7;            // chunk 0..7
    const uint32_t s_so = (uint32_t)s_r * 128 + (uint32_t)((s_c ^ (s_r & 7)) * 16);
    const float*  Xa = X + (size_t)(m_base + s_r) * HIDDEN + (size_t)bz * BLK + s_c * 8;
    const __half* Bg = g_Wt + (size_t)bz * BLK * BLK + (size_t)s_r * BLK + s_c * 8;

    // ---- ldmatrix addressing (warp tile 32x32) ----
    const int a_R  = m0w + (lane & 15);
    const int a_cs = lane >> 4;
    const int a_swr = a_R & 7;
    const uint32_t a_rb = (uint32_t)a_R * 128;
    const int b_N  = n0w + (lane & 7) + ((lane >> 4) & 1) * 8;
    const int b_cs = (lane >> 3) & 1;
    const int b_swr = b_N & 7;
    const uint32_t b_rb = (uint32_t)b_N * 128;

    float acc[2][4][4];
#pragma unroll
    for (int i = 0; i < 2; i++)
#pragma unroll
        for (int j = 0; j < 4; j++)
#pragma unroll
            for (int r = 0; r < 4; r++) acc[i][j][r] = 0.0f;

    // ---- prologue ----
    // A slots 0,1: LDG fp32 + cvt + STS
#pragma unroll
    for (int q = 0; q < 2; q++) {
        char* ab = smem + SMEM_A + q * SLOT_BYTES;
#pragma unroll
        for (int i = 0; i < 2; i++) {
            const float* src = Xa + (size_t)i * 64 * HIDDEN + q * BK;
            float4 f0 = *(const float4*)(src);
            float4 f1 = *(const float4*)(src + 4);
            __half2 h0 = __floats2half2_rn(f0.x, f0.y);
            __half2 h1 = __floats2half2_rn(f0.z, f0.w);
            __half2 h2 = __floats2half2_rn(f1.x, f1.y);
            __half2 h3 = __floats2half2_rn(f1.z, f1.w);
            *(uint4*)(ab + s_so + i * 64 * 128) =
                make_uint4(*(uint32_t*)&h0, *(uint32_t*)&h1,
                           *(uint32_t*)&h2, *(uint32_t*)&h3);
        }
    }
    // B stages 0,1 via cp.async
#pragma unroll
    for (int q = 0; q < 2; q++) {
        uint32_t bb = sb + SMEM_B + q * SLOT_BYTES + s_so;
#pragma unroll
        for (int i = 0; i < 2; i++)
            cp16(bb + i * 64 * 128, Bg + (size_t)i * 64 * BLK + q * BK);
        CP_COMMIT();
    }

    // ---- main loop: 32 flattened (nt, c) stages ----
#pragma unroll 1
    for (int s = 0; s < TOTAL_S; s++) {
        const int c  = s & 7;
        const int nt = s >> 3;

        CP_WAIT1();
        __syncthreads();

        // B prefetch for stage s+2
        if (s + 2 < TOTAL_S) {
            const int s2 = s + 2;
            const int nt2 = s2 >> 3, c2 = s2 & 7;
            uint32_t bb = sb + SMEM_B + (s2 % RING) * SLOT_BYTES + s_so;
#pragma unroll
            for (int i = 0; i < 2; i++)
                cp16(bb + i * 64 * 128,
                     Bg + (size_t)(nt2 * 128 + i * 64) * BLK + c2 * BK);
        }
        CP_COMMIT();

        // A fp32 loads for slot c+2 (first n-tile only)
        float4 af0[2], af1[2];
        const bool afill = (nt == 0) && (c + 2 < NSTAGE);
        if (afill) {
#pragma unroll
            for (int i = 0; i < 2; i++) {
                const float* src = Xa + (size_t)i * 64 * HIDDEN + (c + 2) * BK;
                af0[i] = *(const float4*)(src);
                af1[i] = *(const float4*)(src + 4);
            }
        }

        // ---- compute stage (A slot c, B ring s%RING) ----
        const uint32_t Ab = sb + SMEM_A + c * SLOT_BYTES;
        const uint32_t Bb = sb + SMEM_B + (s % RING) * SLOT_BYTES;
#pragma unroll
        for (int kk = 0; kk < 4; kk++) {
            uint32_t a[2][4];
#pragma unroll
            for (int i = 0; i < 2; i++)
                ldm4(a[i][0], a[i][1], a[i][2], a[i][3],
                     Ab + a_rb + (uint32_t)i * 2048
                        + (uint32_t)(((2 * kk + a_cs) ^ a_swr) * 16));
            uint32_t b[2][4];
#pragma unroll
            for (int j = 0; j < 2; j++)
                ldm4(b[j][0], b[j][1], b[j][2], b[j][3],
                     Bb + b_rb + (uint32_t)j * 2048
                        + (uint32_t)(((2 * kk + b_cs) ^ b_swr) * 16));
#pragma unroll
            for (int i = 0; i < 2; i++)
#pragma unroll
                for (int jj = 0; jj < 4; jj++)
                    mma_f16(acc[i][jj], a[i][0], a[i][1], a[i][2], a[i][3],
                            b[jj >> 1][(jj & 1) * 2], b[jj >> 1][(jj & 1) * 2 + 1]);
        }

        // cvt + STS A slot c+2
        if (afill) {
            char* ab = smem + SMEM_A + (c + 2) * SLOT_BYTES;
#pragma unroll
            for (int i = 0; i < 2; i++) {
                __half2 h0 = __floats2half2_rn(af0[i].x, af0[i].y);
                __half2 h1 = __floats2half2_rn(af0[i].z, af0[i].w);
                __half2 h2 = __floats2half2_rn(af1[i].x, af1[i].y);
                __half2 h3 = __floats2half2_rn(af1[i].z, af1[i].w);
                *(uint4*)(ab + s_so + i * 64 * 128) =
                    make_uint4(*(uint32_t*)&h0, *(uint32_t*)&h1,
                               *(uint32_t*)&h2, *(uint32_t*)&h3);
            }
        }

        // ---- per-n-tile epilogue ----
        if (c == 7) {
            const int orow = m_base + m0w + (lane >> 2);
            const int ocol = bz * BLK + nt * 128 + n0w + (lane & 3) * 2;
#pragma unroll
            for (int i = 0; i < 2; i++) {
#pragma unroll
                for (int jj = 0; jj < 4; jj++) {
                    float2 v0 = make_float2(acc[i][jj][0], acc[i][jj][1]);
                    float2 v1 = make_float2(acc[i][jj][2], acc[i][jj][3]);
                    *(float2*)(O + (size_t)(orow + i * 16)     * HIDDEN + ocol + jj * 8) = v0;
                    *(float2*)(O + (size_t)(orow + i * 16 + 8) * HIDDEN + ocol + jj * 8) = v1;
                    acc[i][jj][0] = 0.0f; acc[i][jj][1] = 0.0f;
                    acc[i][jj][2] = 0.0f; acc[i][jj][3] = 0.0f;
                }
            }
        }
    }
}

extern "C" void kernel_launch(void* const* d_in, const int* in_sizes, int n_in,
                              void* d_out, int out_size)
{
    const float* x = (const float*)d_in[0];
    const float* w = (const float*)d_in[1];
    float* out = (float*)d_out;
    (void)in_sizes; (void)n_in; (void)out_size;

    cudaFuncSetAttribute(tp_fp16_kernel,
                         cudaFuncAttributeMaxDynamicSharedMemorySize, SMEM_TOTAL);

    transpose_half_kernel<<<dim3(BLK / 32, BLK / 32, NB), dim3(32, 8)>>>(w);
    tp_fp16_kernel<<<dim3(TOKENS / BM, NB), THREADS, SMEM_TOTAL>>>(x, out);
}

// round 13
// speedup vs baseline: 1.0493x; 1.0493x over previous
#include <cuda_runtime.h>
#include <cuda_fp16.h>
#include <cstdint>

#define TOKENS 16384
#define HIDDEN 4096
#define NB 8
#define BLK 512

#define BM 128
#define BN 64
#define BK 64                // k halfs per stage -> 128B smem rows
#define NSTAGE (BLK / BK)    // 8
#define RING 3
#define THREADS 256

#define A_STAGE_BYTES (BM * BK * 2)   // 16384
#define B_STAGE_BYTES (BN * BK * 2)   // 8192
#define SMEM_A 0
#define SMEM_B (RING * A_STAGE_BYTES)              // 49152
#define SMEM_TOTAL (SMEM_B + RING * B_STAGE_BYTES) // 73728

__device__ __half g_Wt[NB * BLK * BLK];            // W transposed to [n][k], fp16
__device__ __half g_Xh[(size_t)TOKENS * HIDDEN];   // X converted to fp16

__device__ __forceinline__ uint32_t smem_u32(const void* p) {
    uint32_t a;
    asm("{ .reg .u64 t; cvta.to.shared.u64 t, %1; cvt.u32.u64 %0, t; }" : "=r"(a) : "l"(p));
    return a;
}
__device__ __forceinline__ void ldm4(uint32_t& r0, uint32_t& r1, uint32_t& r2,
                                     uint32_t& r3, uint32_t addr) {
    asm volatile("ldmatrix.sync.aligned.m8n8.x4.shared.b16 {%0,%1,%2,%3}, [%4];"
                 : "=r"(r0), "=r"(r1), "=r"(r2), "=r"(r3) : "r"(addr));
}
__device__ __forceinline__ void mma_f16(float c[4], uint32_t a0, uint32_t a1,
                                        uint32_t a2, uint32_t a3,
                                        uint32_t b0, uint32_t b1) {
    asm volatile(
        "mma.sync.aligned.m16n8k16.row.col.f32.f16.f16.f32 "
        "{%0,%1,%2,%3}, {%4,%5,%6,%7}, {%8,%9}, {%0,%1,%2,%3};\n"
        : "+f"(c[0]), "+f"(c[1]), "+f"(c[2]), "+f"(c[3])
        : "r"(a0), "r"(a1), "r"(a2), "r"(a3), "r"(b0), "r"(b1));
}
__device__ __forceinline__ void cp16(uint32_t dst, const void* src) {
    asm volatile("cp.async.cg.shared.global [%0], [%1], 16;" :: "r"(dst), "l"(src) : "memory");
}
#define CP_COMMIT() asm volatile("cp.async.commit_group;" ::: "memory")
#define CP_WAIT1()  asm volatile("cp.async.wait_group 1;" ::: "memory")

// ---------------- prepass 1: X fp32 -> fp16 (384 MB traffic, ~55us) ----------------
__global__ void __launch_bounds__(256)
convert_x_kernel(const float* __restrict__ X) {
    size_t t = (size_t)blockIdx.x * blockDim.x + threadIdx.x;   // 0 .. 8M-1
    const float4* src = (const float4*)X;
    float4 f0 = src[2 * t];
    float4 f1 = src[2 * t + 1];
    __half2 h0 = __floats2half2_rn(f0.x, f0.y);
    __half2 h1 = __floats2half2_rn(f0.z, f0.w);
    __half2 h2 = __floats2half2_rn(f1.x, f1.y);
    __half2 h3 = __floats2half2_rn(f1.z, f1.w);
    uint4 v = make_uint4(*(uint32_t*)&h0, *(uint32_t*)&h1,
                         *(uint32_t*)&h2, *(uint32_t*)&h3);
    ((uint4*)g_Xh)[t] = v;
}

// ---------------- prepass 2: W transpose + fp16 (~4us) ----------------
__global__ void transpose_half_kernel(const float* __restrict__ W) {
    __shared__ float t[32][33];
    const int z = blockIdx.z;
    const int k0 = blockIdx.x * 32, n0 = blockIdx.y * 32;
    const float* Wz = W + (size_t)z * BLK * BLK;
    __half* Wtz = g_Wt + (size_t)z * BLK * BLK;
    const int tx = threadIdx.x, ty = threadIdx.y;
#pragma unroll
    for (int i = 0; i < 32; i += 8)
        t[ty + i][tx] = Wz[(size_t)(k0 + ty + i) * BLK + n0 + tx];
    __syncthreads();
#pragma unroll
    for (int i = 0; i < 32; i += 8)
        Wtz[(size_t)(n0 + ty + i) * BLK + k0 + tx] = __float2half_rn(t[tx][ty + i]);
}

// ---------------- main kernel: 128x64 tiles, 3 CTAs/SM ----------------
__global__ void __launch_bounds__(THREADS, 3)
tp_fp16_kernel(float* __restrict__ O)
{
    extern __shared__ char smem[];
    const uint32_t sb = smem_u32(smem);
    const int tid  = threadIdx.x;
    const int lane = tid & 31;
    const int wid  = tid >> 5;          // 0..7
    const int m0w  = (wid & 3) * 32;    // 4 m-warps
    const int n0w  = (wid >> 2) * 32;   // 2 n-warps

    // n fastest-varying: co-resident CTAs share the A slice (L2 reuse)
    const int n_base = blockIdx.x * BN;     // 0..448
    const int m_base = blockIdx.y * BM;     // 0..16256
    const int bz     = blockIdx.z;

    // ---- cp.async staging plan: s_r = tid>>3 (0..31), chunk s_c = tid&7 ----
    const int s_r = tid >> 3;
    const int s_c = tid & 7;
    const uint32_t s_so = (uint32_t)s_r * 128 + (uint32_t)((s_c ^ (s_r & 7)) * 16);
    const __half* Axg = g_Xh + (size_t)(m_base + s_r) * HIDDEN + (size_t)bz * BLK + s_c * 8;
    const __half* Bxg = g_Wt + (size_t)bz * BLK * BLK
                             + (size_t)(n_base + s_r) * BLK + s_c * 8;

    // ---- ldmatrix addressing ----
    const int a_R  = m0w + (lane & 15);
    const int a_cs = lane >> 4;
    const int a_swr = a_R & 7;
    const uint32_t a_rb = (uint32_t)a_R * 128;
    const int b_N  = n0w + (lane & 7) + ((lane >> 4) & 1) * 8;
    const int b_cs = (lane >> 3) & 1;
    const int b_swr = b_N & 7;
    const uint32_t b_rb = (uint32_t)b_N * 128;

    float acc[2][4][4];
#pragma unroll
    for (int i = 0; i < 2; i++)
#pragma unroll
        for (int j = 0; j < 4; j++)
#pragma unroll
            for (int r = 0; r < 4; r++) acc[i][j][r] = 0.0f;

    // ---- prologue: stages 0,1 (A: 4 cp16, B: 2 cp16 per thread) ----
#pragma unroll
    for (int q = 0; q < 2; q++) {
        uint32_t ab = sb + SMEM_A + q * A_STAGE_BYTES + s_so;
        uint32_t bb = sb + SMEM_B + q * B_STAGE_BYTES + s_so;
#pragma unroll
        for (int i = 0; i < 4; i++)
            cp16(ab + i * 32 * 128, Axg + (size_t)i * 32 * HIDDEN + q * BK);
#pragma unroll
        for (int i = 0; i < 2; i++)
            cp16(bb + i * 32 * 128, Bxg + (size_t)i * 32 * BLK + q * BK);
        CP_COMMIT();
    }

    // ---- main loop: 8 K-stages ----
#pragma unroll 1
    for (int c = 0; c < NSTAGE; c++) {
        CP_WAIT1();
        __syncthreads();

        if (c + 2 < NSTAGE) {
            const int sl = (c + 2) % RING;
            uint32_t ab = sb + SMEM_A + sl * A_STAGE_BYTES + s_so;
            uint32_t bb = sb + SMEM_B + sl * B_STAGE_BYTES + s_so;
#pragma unroll
            for (int i = 0; i < 4; i++)
                cp16(ab + i * 32 * 128, Axg + (size_t)i * 32 * HIDDEN + (c + 2) * BK);
#pragma unroll
            for (int i = 0; i < 2; i++)
                cp16(bb + i * 32 * 128, Bxg + (size_t)i * 32 * BLK + (c + 2) * BK);
        }
        CP_COMMIT();

        const uint32_t Ab = sb + SMEM_A + (c % RING) * A_STAGE_BYTES;
        const uint32_t Bb = sb + SMEM_B + (c % RING) * B_STAGE_BYTES;
#pragma unroll
        for (int kk = 0; kk < 4; kk++) {
            uint32_t a[2][4];
#pragma unroll
            for (int i = 0; i < 2; i++)
                ldm4(a[i][0], a[i][1], a[i][2], a[i][3],
                     Ab + a_rb + (uint32_t)i * 2048
                        + (uint32_t)(((2 * kk + a_cs) ^ a_swr) * 16));
            uint32_t b[2][4];
#pragma unroll
            for (int j = 0; j < 2; j++)
                ldm4(b[j][0], b[j][1], b[j][2], b[j][3],
                     Bb + b_rb + (uint32_t)j * 2048
                        + (uint32_t)(((2 * kk + b_cs) ^ b_swr) * 16));
#pragma unroll
            for (int i = 0; i < 2; i++)
#pragma unroll
                for (int jj = 0; jj < 4; jj++)
                    mma_f16(acc[i][jj], a[i][0], a[i][1], a[i][2], a[i][3],
                            b[jj >> 1][(jj & 1) * 2], b[jj >> 1][(jj & 1) * 2 + 1]);
        }
    }

    // ---- epilogue ----
    const int orow = m_base + m0w + (lane >> 2);
    const int ocol = bz * BLK + n_base + n0w + (lane & 3) * 2;
#pragma unroll
    for (int i = 0; i < 2; i++) {
#pragma unroll
        for (int jj = 0; jj < 4; jj++) {
            float2 v0 = make_float2(acc[i][jj][0], acc[i][jj][1]);
            float2 v1 = make_float2(acc[i][jj][2], acc[i][jj][3]);
            *(float2*)(O + (size_t)(orow + i * 16)     * HIDDEN + ocol + jj * 8) = v0;
            *(float2*)(O + (size_t)(orow + i * 16 + 8) * HIDDEN + ocol + jj * 8) = v1;
        }
    }
}

extern "C" void kernel_launch(void* const* d_in, const int* in_sizes, int n_in,
                              void* d_out, int out_size)
{
    const float* x = (const float*)d_in[0];
    const float* w = (const float*)d_in[1];
    float* out = (float*)d_out;
    (void)in_sizes; (void)n_in; (void)out_size;

    cudaFuncSetAttribute(tp_fp16_kernel,
                         cudaFuncAttributeMaxDynamicSharedMemorySize, SMEM_TOTAL);

    convert_x_kernel<<<(TOKENS * (size_t)HIDDEN / 8 + 255) / 256, 256>>>(x);
    transpose_half_kernel<<<dim3(BLK / 32, BLK / 32, NB), dim3(32, 8)>>>(w);
    tp_fp16_kernel<<<dim3(BLK / BN, TOKENS / BM, NB), THREADS, SMEM_TOTAL>>>(out);
}